// round 8
// baseline (speedup 1.0000x reference)
#include <cuda_runtime.h>
#include <cstdint>

// Problem constants
#define B_  128
#define D_  128
#define T_  2048
#define C_  64
#define ND_ ((long long)(B_ * T_) * D_)     // 33.5M

// Tiling
#define CHUNK       256
#define NCHUNK_TOT  (T_ / CHUNK)            // 8
#define NCHUNKS_BLK 4
#define TSPLIT      (NCHUNK_TOT / NCHUNKS_BLK)  // 2
#define DG          32
#define NDGRP       (D_ / DG)               // 4
#define THREADS     256
#define NCU_TOT     (B_ * NCHUNK_TOT)       // 1024
#define TILE_F      (DG * CHUNK)            // 8192 floats = 32 KB per buffer
#define SMEM_DYN    (2 * TILE_F * 4)        // 64 KB dynamic

// ---------------- device scratch (no allocations allowed) ----------------
__device__ float          g_featsum[C_ * D_];
__device__ int            g_counts[C_];
__device__ float          g_sumsq;
__device__ unsigned short g_list[NCU_TOT * CHUNK];
__device__ unsigned short g_base[NCU_TOT * C_];
__device__ unsigned short g_cnt [NCU_TOT * C_];

// cp.async helpers ---------------------------------------------------------
__device__ __forceinline__ void cp_async16(uint32_t dst_smem, const void* src) {
    asm volatile("cp.async.cg.shared.global [%0], [%1], 16;"
                 :: "r"(dst_smem), "l"(src));
}
__device__ __forceinline__ void cp_commit() {
    asm volatile("cp.async.commit_group;");
}
template <int N>
__device__ __forceinline__ void cp_wait() {
    asm volatile("cp.async.wait_group %0;" :: "n"(N));
}

// swizzled float index within a DGxCHUNK tile (16B store granularity kept;
// column reads land on 8 bank-groups -> <=4-way conflict, negligible volume)
__device__ __forceinline__ int swz(int d, int t) {
    return d * CHUNK + 4 * ((t >> 2) ^ (d & 7)) + (t & 3);
}

// ---------------------------------------------------------------------------
// K1: bucket t-indices by class per (b, chunk). Warp-scan prefix. Also zeroes
// g_featsum / g_counts / g_sumsq. Dtype detect branch-free (MLP 16).
// ---------------------------------------------------------------------------
__global__ void __launch_bounds__(THREADS)
cl_bucket_kernel(const void* __restrict__ label_raw) {
    const int cu  = blockIdx.x;
    const int b   = cu / NCHUNK_TOT;
    const int tc  = cu % NCHUNK_TOT;
    const int tid = threadIdx.x;

    __shared__ int           s_cnt[C_];
    __shared__ int           s_off[C_];
    __shared__ int           s_lab64;
    __shared__ unsigned char s_lab[CHUNK];

    if (cu < (C_ * D_) / THREADS)
        g_featsum[cu * THREADS + tid] = 0.0f;
    if (cu == 0) {
        if (tid < C_) g_counts[tid] = 0;
        if (tid == 0) g_sumsq = 0.0f;
    }
    if (tid < C_) s_cnt[tid] = 0;

    // int64 vs int32 detect: 16 independent loads, no serial chain
    if (tid == 0) {
        const long long* l = (const long long*)label_raw;
        long long bad = 0;
        #pragma unroll
        for (int i = 0; i < 16; i++) bad |= (l[i] >> 6);  // 0 iff 0<=v<64
        s_lab64 = (bad == 0);
    }
    __syncthreads();

    const int* __restrict__ lab32 = (const int*)label_raw;
    const int gi  = b * T_ + tc * CHUNK + tid;
    const int lab = s_lab64 ? lab32[2 * gi] : lab32[gi];
    s_lab[tid] = (unsigned char)lab;
    atomicAdd(&s_cnt[lab], 1);
    __syncthreads();

    // warp-scan exclusive prefix over 64 counters (lane i owns 2i, 2i+1)
    if (tid < 32) {
        const int c0 = s_cnt[2 * tid];
        const int c1 = s_cnt[2 * tid + 1];
        int scan = c0 + c1;
        #pragma unroll
        for (int o = 1; o < 32; o <<= 1) {
            int v = __shfl_up_sync(0xFFFFFFFFu, scan, o);
            if (tid >= o) scan += v;
        }
        const int excl = scan - (c0 + c1);
        s_off[2 * tid]     = excl;
        s_off[2 * tid + 1] = excl + c0;
        g_base[cu * C_ + 2 * tid]     = (unsigned short)excl;
        g_base[cu * C_ + 2 * tid + 1] = (unsigned short)(excl + c0);
        g_cnt [cu * C_ + 2 * tid]     = (unsigned short)c0;
        g_cnt [cu * C_ + 2 * tid + 1] = (unsigned short)c1;
    }
    __syncthreads();

    const int pos = atomicAdd(&s_off[s_lab[tid]], 1);
    g_list[cu * CHUNK + pos] = (unsigned short)tid;
}

// ---------------------------------------------------------------------------
// K2: streaming pass. cp.async double-buffered GMEM->SMEM (no registers in
// the data path, no spills), conflict-light class-ordered gather, sumsq
// computed inside the gather (each element visited exactly once).
// ---------------------------------------------------------------------------
__global__ void __launch_bounds__(THREADS, 3)
cl_main_kernel(const float* __restrict__ feature) {
    extern __shared__ float s_tile[];       // [2][TILE_F]

    const int bid  = blockIdx.x;
    const int ts   = bid % TSPLIT;
    const int dgrp = (bid / TSPLIT) % NDGRP;
    const int b    = bid / (TSPLIT * NDGRP);
    const int d0   = dgrp * DG;
    const int tid  = threadIdx.x;
    const int w    = tid >> 5;
    const int lane = tid & 31;

    __shared__ unsigned short s_list[CHUNK];
    __shared__ unsigned short s_base[C_];
    __shared__ unsigned short s_cnt[C_];
    __shared__ float          s_red[THREADS / 32];

    // cp.async geometry: thread -> (row d, unit stride 8 over 64 16B units)
    const int cpd = tid >> 3;               // 0..31
    const int u0  = tid & 7;                // 0..7
    const float* __restrict__ frow =
        feature + ((size_t)b * D_ + d0 + cpd) * T_
                + (size_t)ts * NCHUNKS_BLK * CHUNK;
    const uint32_t tile_sh = (uint32_t)__cvta_generic_to_shared(s_tile);
    const int cu0 = b * NCHUNK_TOT + ts * NCHUNKS_BLK;

    // issue one chunk into buffer `buf`
    auto issue_chunk = [&](int ch, int buf) {
        const float* src_base = frow + ch * CHUNK;
        const uint32_t dst_base = tile_sh + (uint32_t)(buf * TILE_F) * 4u;
        #pragma unroll
        for (int j = 0; j < 8; j++) {
            const int u = u0 + 8 * j;
            cp_async16(dst_base + 4u * (uint32_t)(cpd * CHUNK + 4 * (u ^ (cpd & 7))),
                       src_base + 4 * u);
        }
        cp_commit();
    };

    // prologue: both buffers in flight, lists for chunk 0 in regs
    issue_chunk(0, 0);
    issue_chunk(1, 1);
    unsigned short rlist = g_list[cu0 * CHUNK + tid];
    unsigned short rbase = 0, rcnt = 0;
    if (tid < C_) {
        rbase = g_base[cu0 * C_ + tid];
        rcnt  = g_cnt [cu0 * C_ + tid];
    }

    float acc[8];
    #pragma unroll
    for (int i = 0; i < 8; i++) acc[i] = 0.0f;
    float sumsq   = 0.0f;
    int   cnt_acc = 0;
    const bool do_cnt = (dgrp == 0);

    for (int ch = 0; ch < NCHUNKS_BLK; ch++) {
        // stage lists (protected by prev iteration's post-gather sync)
        s_list[tid] = rlist;
        if (tid < C_) {
            s_base[tid] = rbase;
            s_cnt [tid] = rcnt;
            if (do_cnt) cnt_acc += (int)rcnt;
        }

        // tile for this chunk ready
        if (ch < NCHUNKS_BLK - 1) cp_wait<1>(); else cp_wait<0>();
        __syncthreads();

        // prefetch next chunk's lists (LDG overlaps gather)
        if (ch + 1 < NCHUNKS_BLK) {
            const int cu = cu0 + ch + 1;
            rlist = g_list[cu * CHUNK + tid];
            if (tid < C_) {
                rbase = g_base[cu * C_ + tid];
                rcnt  = g_cnt [cu * C_ + tid];
            }
        }

        // gather: warp w owns classes {w, w+8,...}; lane = d offset
        const float* __restrict__ tb = s_tile + (ch & 1) * TILE_F;
        #pragma unroll
        for (int ci = 0; ci < 8; ci++) {
            const int c    = w + 8 * ci;
            const int cnt  = s_cnt[c];
            const int base = s_base[c];
            float a = acc[ci];
            int k = 0;
            for (; k + 4 <= cnt; k += 4) {
                const int t0 = s_list[base + k + 0];
                const int t1 = s_list[base + k + 1];
                const int t2 = s_list[base + k + 2];
                const int t3 = s_list[base + k + 3];
                const float v0 = tb[swz(lane, t0)];
                const float v1 = tb[swz(lane, t1)];
                const float v2 = tb[swz(lane, t2)];
                const float v3 = tb[swz(lane, t3)];
                a += v0; sumsq += v0 * v0;
                a += v1; sumsq += v1 * v1;
                a += v2; sumsq += v2 * v2;
                a += v3; sumsq += v3 * v3;
            }
            for (; k < cnt; k++) {
                const float v = tb[swz(lane, s_list[base + k])];
                a += v; sumsq += v * v;
            }
            acc[ci] = a;
        }
        __syncthreads();                    // buffer free for refill

        if (ch + 2 < NCHUNKS_BLK) issue_chunk(ch + 2, ch & 1);
    }

    // merge register accumulators -> global featsum
    #pragma unroll
    for (int ci = 0; ci < 8; ci++) {
        const int c = w + 8 * ci;
        atomicAdd(&g_featsum[c * D_ + d0 + lane], acc[ci]);
    }
    if (do_cnt && tid < C_) atomicAdd(&g_counts[tid], cnt_acc);

    // block-reduce sumsq
    #pragma unroll
    for (int o = 16; o > 0; o >>= 1)
        sumsq += __shfl_down_sync(0xFFFFFFFFu, sumsq, o);
    if (lane == 0) s_red[w] = sumsq;
    __syncthreads();
    if (tid == 0) {
        float s = 0.0f;
        #pragma unroll
        for (int i = 0; i < THREADS / 32; i++) s += s_red[i];
        atomicAdd(&g_sumsq, s);
    }
}

// ---------------------------------------------------------------------------
// K3: finalize.
//   difference[c,d] = cnt>0 ? centers - featsum/cnt : 0
//   loss = (sumsq + sum_c cnt*||ctr||^2 - 2*sum ctr.featsum) / (N*D)
// out[0] = loss, out[1..8192] = difference row-major [C][D].
// ---------------------------------------------------------------------------
__global__ void __launch_bounds__(1024)
cl_finalize_kernel(const float* __restrict__ centers,
                   float* __restrict__ out) {
    __shared__ float s_warp[32];
    const int tid = threadIdx.x;

    float local = 0.0f;
    #pragma unroll
    for (int i = tid; i < C_ * D_; i += 1024) {
        const int   c   = i >> 7;
        const float ctr = centers[i];
        const float fs  = g_featsum[i];
        const int   cnt = g_counts[c];
        out[1 + i] = (cnt > 0) ? (ctr - fs / (float)cnt) : 0.0f;
        local += (float)cnt * ctr * ctr - 2.0f * ctr * fs;
    }

    #pragma unroll
    for (int o = 16; o > 0; o >>= 1)
        local += __shfl_down_sync(0xFFFFFFFFu, local, o);
    if ((tid & 31) == 0) s_warp[tid >> 5] = local;
    __syncthreads();

    if (tid == 0) {
        float cross = 0.0f;
        #pragma unroll
        for (int i = 0; i < 32; i++) cross += s_warp[i];
        out[0] = (g_sumsq + cross) / (float)ND_;
    }
}

// ---------------------------------------------------------------------------
extern "C" void kernel_launch(void* const* d_in, const int* in_sizes, int n_in,
                              void* d_out, int out_size) {
    const float* feature = (const float*)d_in[0];
    const void*  label   = d_in[1];
    const float* centers = (const float*)d_in[2];
    float* out = (float*)d_out;

    cudaFuncSetAttribute(cl_main_kernel,
                         cudaFuncAttributeMaxDynamicSharedMemorySize, SMEM_DYN);

    cl_bucket_kernel<<<NCU_TOT, THREADS>>>(label);
    cl_main_kernel<<<B_ * NDGRP * TSPLIT, THREADS, SMEM_DYN>>>(feature);
    cl_finalize_kernel<<<1, 1024>>>(centers, out);
}

// round 9
// speedup vs baseline: 1.0064x; 1.0064x over previous
#include <cuda_runtime.h>
#include <cstdint>

// Problem constants
#define B_  128
#define D_  128
#define T_  2048
#define C_  64
#define ND_ ((long long)(B_ * T_) * D_)     // 33.5M

// Tiling (R4-proven K2 geometry)
#define CHUNK       256
#define NCHUNK_TOT  (T_ / CHUNK)            // 8
#define NCHUNKS_BLK 4
#define TSPLIT      (NCHUNK_TOT / NCHUNKS_BLK)  // 2
#define DG          32
#define NDGRP       (D_ / DG)               // 4
#define ST          (CHUNK + 1)             // odd stride: conflict-free both ways
#define THREADS     256
#define NCU_TOT     (B_ * NCHUNK_TOT)       // 1024
#define NBLK_MAIN   (B_ * NDGRP * TSPLIT)   // 1024

// ---------------- device scratch (no allocations allowed) ----------------
__device__ float          g_featsum[C_ * D_];
__device__ int            g_counts[C_];
__device__ float          g_sumsq;
__device__ unsigned int   g_done;
__device__ unsigned short g_list[NCU_TOT * CHUNK];
__device__ unsigned short g_base[NCU_TOT * C_];
__device__ unsigned short g_cnt [NCU_TOT * C_];

// ---------------------------------------------------------------------------
// K1: bucket t-indices by class per (b, chunk). Warp-scan prefix. Zeroes
// g_featsum / g_counts / g_sumsq / g_done. Dtype detect branch-free (MLP 16).
// ---------------------------------------------------------------------------
__global__ void __launch_bounds__(THREADS)
cl_bucket_kernel(const void* __restrict__ label_raw) {
    const int cu  = blockIdx.x;
    const int b   = cu / NCHUNK_TOT;
    const int tc  = cu % NCHUNK_TOT;
    const int tid = threadIdx.x;

    __shared__ int           s_cnt[C_];
    __shared__ int           s_off[C_];
    __shared__ int           s_lab64;
    __shared__ unsigned char s_lab[CHUNK];

    if (cu < (C_ * D_) / THREADS)
        g_featsum[cu * THREADS + tid] = 0.0f;
    if (cu == 0) {
        if (tid < C_) g_counts[tid] = 0;
        if (tid == 0) { g_sumsq = 0.0f; g_done = 0u; }
    }
    if (tid < C_) s_cnt[tid] = 0;

    // int64 vs int32 detect: 16 INDEPENDENT loads (no serial LDG chain)
    if (tid == 0) {
        const long long* l = (const long long*)label_raw;
        long long bad = 0;
        #pragma unroll
        for (int i = 0; i < 16; i++) bad |= (l[i] >> 6);   // 0 iff 0<=v<64
        s_lab64 = (bad == 0);
    }
    __syncthreads();

    const int* __restrict__ lab32 = (const int*)label_raw;
    const int gi  = b * T_ + tc * CHUNK + tid;
    const int lab = s_lab64 ? lab32[2 * gi] : lab32[gi];
    s_lab[tid] = (unsigned char)lab;
    atomicAdd(&s_cnt[lab], 1);
    __syncthreads();

    // warp-scan exclusive prefix over 64 counters (lane i owns 2i, 2i+1)
    if (tid < 32) {
        const int c0 = s_cnt[2 * tid];
        const int c1 = s_cnt[2 * tid + 1];
        int scan = c0 + c1;
        #pragma unroll
        for (int o = 1; o < 32; o <<= 1) {
            int v = __shfl_up_sync(0xFFFFFFFFu, scan, o);
            if (tid >= o) scan += v;
        }
        const int excl = scan - (c0 + c1);
        s_off[2 * tid]     = excl;
        s_off[2 * tid + 1] = excl + c0;
        g_base[cu * C_ + 2 * tid]     = (unsigned short)excl;
        g_base[cu * C_ + 2 * tid + 1] = (unsigned short)(excl + c0);
        g_cnt [cu * C_ + 2 * tid]     = (unsigned short)c0;
        g_cnt [cu * C_ + 2 * tid + 1] = (unsigned short)c1;
    }
    __syncthreads();

    const int pos = atomicAdd(&s_off[s_lab[tid]], 1);
    g_list[cu * CHUNK + pos] = (unsigned short)tid;
}

// ---------------------------------------------------------------------------
// K2: streaming pass (R4 structure, unchanged) + fused finalize in the last
// block to finish. Register-pipelined chunks, conflict-free stride-257 tile,
// zero atomics in the hot path.
// ---------------------------------------------------------------------------
__global__ void __launch_bounds__(THREADS, 4)
cl_main_kernel(const float* __restrict__ feature,
               const float* __restrict__ centers,
               float* __restrict__ out) {
    const int bid  = blockIdx.x;
    const int ts   = bid % TSPLIT;
    const int dgrp = (bid / TSPLIT) % NDGRP;
    const int b    = bid / (TSPLIT * NDGRP);
    const int d0   = dgrp * DG;
    const int tid  = threadIdx.x;
    const int w    = tid >> 5;
    const int lane = tid & 31;

    __shared__ float          s_tile[DG * ST];
    __shared__ unsigned short s_list[CHUNK];
    __shared__ unsigned short s_base[C_];
    __shared__ unsigned short s_cnt[C_];
    __shared__ float          s_red[THREADS / 32];
    __shared__ int            s_last;

    const float* __restrict__ fblk =
        feature + ((size_t)b * D_ + d0) * T_ + (size_t)ts * NCHUNKS_BLK * CHUNK;
    const int cu0 = b * NCHUNK_TOT + ts * NCHUNKS_BLK;

    float r[DG];
    unsigned short rlist = 0, rbase = 0, rcnt = 0;

    // prologue: prefetch chunk 0
    {
        const float* __restrict__ fb = fblk;
        #pragma unroll
        for (int dg = 0; dg < DG; dg++) r[dg] = __ldg(&fb[dg * T_ + tid]);
        rlist = g_list[cu0 * CHUNK + tid];
        if (tid < C_) {
            rbase = g_base[cu0 * C_ + tid];
            rcnt  = g_cnt [cu0 * C_ + tid];
        }
    }

    float acc[8];
    #pragma unroll
    for (int i = 0; i < 8; i++) acc[i] = 0.0f;
    float sumsq   = 0.0f;
    int   cnt_acc = 0;
    const bool do_cnt = (dgrp == 0);

    for (int ch = 0; ch < NCHUNKS_BLK; ch++) {
        if (ch) __syncthreads();            // tile free (prev gather done)

        // stage regs -> shared (conflict-free: stride-1 across lanes)
        #pragma unroll
        for (int dg = 0; dg < DG; dg++) {
            const float v = r[dg];
            sumsq += v * v;
            s_tile[dg * ST + tid] = v;
        }
        s_list[tid] = rlist;
        if (tid < C_) {
            s_base[tid] = rbase;
            s_cnt [tid] = rcnt;
            if (do_cnt) cnt_acc += (int)rcnt;
        }
        __syncthreads();                    // tile + lists ready

        // prefetch chunk ch+1 (independent of gather -> overlaps it)
        if (ch + 1 < NCHUNKS_BLK) {
            const float* __restrict__ fb = fblk + (ch + 1) * CHUNK;
            #pragma unroll
            for (int dg = 0; dg < DG; dg++) r[dg] = __ldg(&fb[dg * T_ + tid]);
            const int cu = cu0 + ch + 1;
            rlist = g_list[cu * CHUNK + tid];
            if (tid < C_) {
                rbase = g_base[cu * C_ + tid];
                rcnt  = g_cnt [cu * C_ + tid];
            }
        }

        // gather: warp w owns classes {w, w+8, ..., w+56}; lane = d offset
        #pragma unroll
        for (int ci = 0; ci < 8; ci++) {
            const int c    = w + 8 * ci;
            const int cnt  = s_cnt[c];
            const int base = s_base[c];
            float a = acc[ci];
            int k = 0;
            for (; k + 4 <= cnt; k += 4) {
                const int t0 = s_list[base + k + 0];
                const int t1 = s_list[base + k + 1];
                const int t2 = s_list[base + k + 2];
                const int t3 = s_list[base + k + 3];
                a += s_tile[lane * ST + t0];
                a += s_tile[lane * ST + t1];
                a += s_tile[lane * ST + t2];
                a += s_tile[lane * ST + t3];
            }
            for (; k < cnt; k++)
                a += s_tile[lane * ST + s_list[base + k]];
            acc[ci] = a;
        }
    }

    // merge register accumulators -> global featsum
    #pragma unroll
    for (int ci = 0; ci < 8; ci++) {
        const int c = w + 8 * ci;
        atomicAdd(&g_featsum[c * D_ + d0 + lane], acc[ci]);
    }
    if (do_cnt && tid < C_) atomicAdd(&g_counts[tid], cnt_acc);

    // block-reduce sumsq
    #pragma unroll
    for (int o = 16; o > 0; o >>= 1)
        sumsq += __shfl_down_sync(0xFFFFFFFFu, sumsq, o);
    if (lane == 0) s_red[w] = sumsq;
    __syncthreads();
    if (tid == 0) {
        float s = 0.0f;
        #pragma unroll
        for (int i = 0; i < THREADS / 32; i++) s += s_red[i];
        atomicAdd(&g_sumsq, s);
        __threadfence();                    // publish all our updates
        const unsigned int prev = atomicAdd(&g_done, 1u);
        s_last = (prev == (unsigned int)(NBLK_MAIN - 1));
    }
    __syncthreads();

    // ---- fused finalize: last block to finish computes difference + loss ----
    if (s_last) {
        __threadfence();                    // acquire all blocks' updates
        float local = 0.0f;
        #pragma unroll
        for (int i = tid; i < C_ * D_; i += THREADS) {
            const int   c   = i >> 7;       // i / D_
            const float ctr = centers[i];
            const float fs  = g_featsum[i];
            const int   cnt = g_counts[c];
            out[1 + i] = (cnt > 0) ? (ctr - fs / (float)cnt) : 0.0f;
            local += (float)cnt * ctr * ctr - 2.0f * ctr * fs;
        }
        #pragma unroll
        for (int o = 16; o > 0; o >>= 1)
            local += __shfl_down_sync(0xFFFFFFFFu, local, o);
        if (lane == 0) s_red[w] = local;
        __syncthreads();
        if (tid == 0) {
            float cross = 0.0f;
            #pragma unroll
            for (int i = 0; i < THREADS / 32; i++) cross += s_red[i];
            out[0] = (g_sumsq + cross) / (float)ND_;
        }
    }
}

// ---------------------------------------------------------------------------
extern "C" void kernel_launch(void* const* d_in, const int* in_sizes, int n_in,
                              void* d_out, int out_size) {
    const float* feature = (const float*)d_in[0];
    const void*  label   = d_in[1];
    const float* centers = (const float*)d_in[2];
    float* out = (float*)d_out;

    cl_bucket_kernel<<<NCU_TOT, THREADS>>>(label);
    cl_main_kernel<<<NBLK_MAIN, THREADS>>>(feature, centers, out);
}